// round 4
// baseline (speedup 1.0000x reference)
#include <cuda_runtime.h>
#include <cuda_bf16.h>

// DataWindowLoss: mean(|box5(x) - box5(y)|), x,y: [64,1,512,512] f32.
// box5(x)-box5(y) = box5(x-y); separable 5x5 uniform kernel.
// Register-streaming: thread = one float4 column-group; per row: load d,
// horizontal 5-sum via shfl_up, vertical sliding sum in a 5-slot register
// ring. 25 row-chunks/image for occupancy; interior chunks take a fully
// unguarded path. Cols 512..515 handled by tiny edge blocks.

#define B_IMGS 64
#define H 512
#define W 512
#define OH 516
#define OW 516

#define THREADS 128
#define CHUNK_ROWS 21
#define NCHUNK 25                   // 25*21 = 525 >= 516
#define SCANR  (CHUNK_ROWS + 4)     // 25, multiple of 5
#define NBLOCKS ((NCHUNK + 1) * B_IMGS)   // 1664

__device__ double g_accum;      // zero-initialized
__device__ unsigned g_count;    // zero-initialized

__device__ __forceinline__ float warp_red(float v) {
    #pragma unroll
    for (int o = 16; o > 0; o >>= 1) v += __shfl_down_sync(0xffffffffu, v, o);
    return v;
}

__device__ __forceinline__ float4 f4zero() { return make_float4(0.f, 0.f, 0.f, 0.f); }

template <bool GUARD>
__device__ __forceinline__ float scan_chunk(const float4* __restrict__ x4,
                                            const float4* __restrict__ y4,
                                            int base_r, int g, int lane, int imax) {
    float4 ring[5];
    #pragma unroll
    for (int k = 0; k < 5; ++k) ring[k] = f4zero();
    float4 vs = f4zero();
    float acc = 0.f;

    #pragma unroll 1
    for (int ib = 0; ib < SCANR; ib += 5) {
        #pragma unroll
        for (int j = 0; j < 5; ++j) {
            const int i = ib + j;
            const int r = base_r + i;
            const bool rowok = !GUARD || ((r >= 0) && (r < H));
            float4 cur = f4zero();
            if (rowok) {
                float4 a = x4[(size_t)r * (W / 4) + g];
                float4 b = y4[(size_t)r * (W / 4) + g];
                cur.x = a.x - b.x; cur.y = a.y - b.y;
                cur.z = a.z - b.z; cur.w = a.w - b.w;
            }
            float4 prv;
            prv.x = __shfl_up_sync(0xffffffffu, cur.x, 1);
            prv.y = __shfl_up_sync(0xffffffffu, cur.y, 1);
            prv.z = __shfl_up_sync(0xffffffffu, cur.z, 1);
            prv.w = __shfl_up_sync(0xffffffffu, cur.w, 1);
            if (lane == 0) {
                prv = f4zero();
                if (rowok && g > 0) {
                    float4 a = x4[(size_t)r * (W / 4) + g - 1];
                    float4 b = y4[(size_t)r * (W / 4) + g - 1];
                    prv.x = a.x - b.x; prv.y = a.y - b.y;
                    prv.z = a.z - b.z; prv.w = a.w - b.w;
                }
            }
            float4 hv;
            const float p23 = prv.z + prv.w;
            const float c01 = cur.x + cur.y;
            hv.x = prv.x + prv.y + p23 + cur.x;
            hv.y = prv.y + p23 + c01;
            hv.z = p23 + c01 + cur.z;
            hv.w = prv.w + c01 + cur.z + cur.w;
            vs.x += hv.x - ring[j].x; vs.y += hv.y - ring[j].y;
            vs.z += hv.z - ring[j].z; vs.w += hv.w - ring[j].w;
            ring[j] = hv;
            if (i >= 4) {
                if (!GUARD || (i <= imax))
                    acc += fabsf(vs.x) + fabsf(vs.y) + fabsf(vs.z) + fabsf(vs.w);
            }
        }
    }
    return acc;
}

__global__ void __launch_bounds__(THREADS, 8)
box_abs_kernel(const float* __restrict__ x, const float* __restrict__ y,
               float* __restrict__ out) {
    const int tid  = threadIdx.x;
    const int lane = tid & 31;
    const int img  = blockIdx.y;
    const size_t ibase = (size_t)img * H * (W / 4);
    const float4* x4 = reinterpret_cast<const float4*>(x) + ibase;
    const float4* y4 = reinterpret_cast<const float4*>(y) + ibase;

    float acc = 0.f;

    if (blockIdx.x < NCHUNK) {
        const int R0     = blockIdx.x * CHUNK_ROWS;
        const int base_r = R0 - 4;
        // interior iff all input rows [R0-4, R0+SCANR-5] within [0,H) and
        // all output rows [R0, R0+CHUNK_ROWS) < OH
        const bool interior = (base_r >= 0) && (R0 + CHUNK_ROWS - 1 < H) &&
                              (R0 + CHUNK_ROWS <= OH);
        if (interior)
            acc = scan_chunk<false>(x4, y4, base_r, tid, lane, SCANR);
        else
            acc = scan_chunk<true>(x4, y4, base_r, tid, lane, OH - R0 + 3);
    } else {
        // ---- edge path: output cols 512..515 (need only d-group 127) ----
        for (int pass = 0; pass < 2; ++pass) {
            if (pass == 1 && tid != 0) break;
            const int a = (pass == 0) ? 4 * tid : 512;
            float hx[8], hy[8], hz[8], hw[8];
            #pragma unroll
            for (int k = 0; k < 8; ++k) {
                const int r = a - 4 + k;
                float4 d = f4zero();
                if (r >= 0 && r < H) {
                    float4 av = x4[(size_t)r * (W / 4) + 127];
                    float4 bv = y4[(size_t)r * (W / 4) + 127];
                    d.x = av.x - bv.x; d.y = av.y - bv.y;
                    d.z = av.z - bv.z; d.w = av.w - bv.w;
                }
                hx[k] = d.x + d.y + d.z + d.w;   // h[512]
                hy[k] = d.y + d.z + d.w;         // h[513]
                hz[k] = d.z + d.w;               // h[514]
                hw[k] = d.w;                     // h[515]
            }
            #pragma unroll
            for (int j = 0; j < 4; ++j) {
                float sx = 0.f, sy = 0.f, sz = 0.f, sw = 0.f;
                #pragma unroll
                for (int k = j; k < j + 5; ++k) {
                    sx += hx[k]; sy += hy[k]; sz += hz[k]; sw += hw[k];
                }
                acc += fabsf(sx) + fabsf(sy) + fabsf(sz) + fabsf(sw);
            }
        }
    }

    // ---- block reduce + fused finalize ----
    __shared__ float wsum[THREADS / 32];
    acc = warp_red(acc);
    if (lane == 0) wsum[tid >> 5] = acc;
    __syncthreads();
    if (tid == 0) {
        float v = 0.f;
        #pragma unroll
        for (int i = 0; i < THREADS / 32; ++i) v += wsum[i];
        atomicAdd(&g_accum, (double)v);
        __threadfence();
        unsigned prev_cnt = atomicAdd(&g_count, 1u);
        if (prev_cnt == NBLOCKS - 1) {
            __threadfence();
            double total = atomicAdd(&g_accum, 0.0);
            const double scale = 1.0 / (25.0 * (double)B_IMGS * (double)OH * (double)OW);
            out[0] = (float)(total * scale);
            g_accum = 0.0;          // reset for next graph replay
            __threadfence();
            g_count = 0u;
        }
    }
}

extern "C" void kernel_launch(void* const* d_in, const int* in_sizes, int n_in,
                              void* d_out, int out_size) {
    (void)in_sizes; (void)n_in; (void)out_size;
    const float* x = (const float*)d_in[0];
    const float* y = (const float*)d_in[1];
    float* out = (float*)d_out;

    dim3 grid(NCHUNK + 1, B_IMGS);
    box_abs_kernel<<<grid, THREADS>>>(x, y, out);
}

// round 5
// speedup vs baseline: 1.0839x; 1.0839x over previous
#include <cuda_runtime.h>
#include <cuda_bf16.h>

// DataWindowLoss: mean(|box5(x) - box5(y)|), x,y: [64,1,512,512] f32.
// box5(x)-box5(y) = box5(x-y); separable 5x5 uniform kernel.
// Branch-free register streaming: thread = one float4 column-group; per row
// it loads groups g and g-1 of both x and y (g-1 hits L1: same lines as the
// warp's g load), forms horizontal 5-sums in registers, and keeps the
// vertical 5-row sliding sum in a register ring. No shuffles, no branches
// in the hot loop -> 20 independent LDG.128 per 5-row group (full MLP).
// Cols 512..515 handled by tiny edge blocks.

#define B_IMGS 64
#define H 512
#define W 512
#define OH 516
#define OW 516

#define THREADS 128
#define CHUNK_ROWS 31
#define NCHUNK 17                   // 17*31 = 527 >= 516
#define SCANR  (CHUNK_ROWS + 4)     // 35, multiple of 5
#define NBLOCKS ((NCHUNK + 1) * B_IMGS)   // 1152

__device__ double g_accum;      // zero-initialized
__device__ unsigned g_count;    // zero-initialized

__device__ __forceinline__ float warp_red(float v) {
    #pragma unroll
    for (int o = 16; o > 0; o >>= 1) v += __shfl_down_sync(0xffffffffu, v, o);
    return v;
}

__device__ __forceinline__ float4 f4zero() { return make_float4(0.f, 0.f, 0.f, 0.f); }

template <bool GUARD>
__device__ __forceinline__ float scan_chunk(const float4* __restrict__ x4,
                                            const float4* __restrict__ y4,
                                            int base_r, int g, int imax) {
    const int   gp = (g > 0) ? (g - 1) : 0;     // clamped; zeroed by gmask
    const float gmask = (g > 0) ? 1.f : 0.f;

    float4 ring[5];
    #pragma unroll
    for (int k = 0; k < 5; ++k) ring[k] = f4zero();
    float4 vs = f4zero();
    float acc = 0.f;

    #pragma unroll 1
    for (int ib = 0; ib < SCANR; ib += 5) {
        #pragma unroll
        for (int j = 0; j < 5; ++j) {
            const int i = ib + j;
            const int r = base_r + i;
            int rc = r;
            float rmask = 1.f;
            if (GUARD) {
                rc = min(max(r, 0), H - 1);
                rmask = (r >= 0 && r < H) ? 1.f : 0.f;
            }
            const size_t ro = (size_t)rc * (W / 4);
            const float4 a  = x4[ro + g];
            const float4 b  = y4[ro + g];
            const float4 ap = x4[ro + gp];
            const float4 bp = y4[ro + gp];

            float4 cur, prv;
            cur.x = a.x - b.x; cur.y = a.y - b.y;
            cur.z = a.z - b.z; cur.w = a.w - b.w;
            const float pm = gmask * rmask;
            prv.x = (ap.x - bp.x) * pm; prv.y = (ap.y - bp.y) * pm;
            prv.z = (ap.z - bp.z) * pm; prv.w = (ap.w - bp.w) * pm;
            if (GUARD) {
                cur.x *= rmask; cur.y *= rmask;
                cur.z *= rmask; cur.w *= rmask;
            }

            float4 hv;
            const float p23 = prv.z + prv.w;
            const float c01 = cur.x + cur.y;
            hv.x = prv.x + prv.y + p23 + cur.x;
            hv.y = prv.y + p23 + c01;
            hv.z = p23 + c01 + cur.z;
            hv.w = prv.w + c01 + cur.z + cur.w;

            vs.x += hv.x - ring[j].x; vs.y += hv.y - ring[j].y;
            vs.z += hv.z - ring[j].z; vs.w += hv.w - ring[j].w;
            ring[j] = hv;

            if (i >= 4) {
                if (!GUARD || (i <= imax))
                    acc += fabsf(vs.x) + fabsf(vs.y) + fabsf(vs.z) + fabsf(vs.w);
            }
        }
    }
    return acc;
}

__global__ void __launch_bounds__(THREADS)
box_abs_kernel(const float* __restrict__ x, const float* __restrict__ y,
               float* __restrict__ out) {
    const int tid  = threadIdx.x;
    const int lane = tid & 31;
    const int img  = blockIdx.y;
    const size_t ibase = (size_t)img * H * (W / 4);
    const float4* x4 = reinterpret_cast<const float4*>(x) + ibase;
    const float4* y4 = reinterpret_cast<const float4*>(y) + ibase;

    float acc = 0.f;

    if (blockIdx.x < NCHUNK) {
        const int R0     = blockIdx.x * CHUNK_ROWS;
        const int base_r = R0 - 4;
        const bool interior = (base_r >= 0) && (R0 + CHUNK_ROWS - 1 < H) &&
                              (R0 + CHUNK_ROWS <= OH);
        if (interior)
            acc = scan_chunk<false>(x4, y4, base_r, tid, SCANR);
        else
            acc = scan_chunk<true>(x4, y4, base_r, tid, OH - R0 + 3);
    } else {
        // ---- edge path: output cols 512..515 (need only d-group 127) ----
        for (int pass = 0; pass < 2; ++pass) {
            if (pass == 1 && tid != 0) break;
            const int a = (pass == 0) ? 4 * tid : 512;
            float hx[8], hy[8], hz[8], hw[8];
            #pragma unroll
            for (int k = 0; k < 8; ++k) {
                const int r = a - 4 + k;
                float4 d = f4zero();
                if (r >= 0 && r < H) {
                    float4 av = x4[(size_t)r * (W / 4) + 127];
                    float4 bv = y4[(size_t)r * (W / 4) + 127];
                    d.x = av.x - bv.x; d.y = av.y - bv.y;
                    d.z = av.z - bv.z; d.w = av.w - bv.w;
                }
                hx[k] = d.x + d.y + d.z + d.w;   // h[512]
                hy[k] = d.y + d.z + d.w;         // h[513]
                hz[k] = d.z + d.w;               // h[514]
                hw[k] = d.w;                     // h[515]
            }
            #pragma unroll
            for (int j = 0; j < 4; ++j) {
                float sx = 0.f, sy = 0.f, sz = 0.f, sw = 0.f;
                #pragma unroll
                for (int k = j; k < j + 5; ++k) {
                    sx += hx[k]; sy += hy[k]; sz += hz[k]; sw += hw[k];
                }
                acc += fabsf(sx) + fabsf(sy) + fabsf(sz) + fabsf(sw);
            }
        }
    }

    // ---- block reduce + fused finalize ----
    __shared__ float wsum[THREADS / 32];
    acc = warp_red(acc);
    if (lane == 0) wsum[tid >> 5] = acc;
    __syncthreads();
    if (tid == 0) {
        float v = 0.f;
        #pragma unroll
        for (int i = 0; i < THREADS / 32; ++i) v += wsum[i];
        atomicAdd(&g_accum, (double)v);
        __threadfence();
        unsigned prev_cnt = atomicAdd(&g_count, 1u);
        if (prev_cnt == NBLOCKS - 1) {
            __threadfence();
            double total = atomicAdd(&g_accum, 0.0);
            const double scale = 1.0 / (25.0 * (double)B_IMGS * (double)OH * (double)OW);
            out[0] = (float)(total * scale);
            g_accum = 0.0;          // reset for next graph replay
            __threadfence();
            g_count = 0u;
        }
    }
}

extern "C" void kernel_launch(void* const* d_in, const int* in_sizes, int n_in,
                              void* d_out, int out_size) {
    (void)in_sizes; (void)n_in; (void)out_size;
    const float* x = (const float*)d_in[0];
    const float* y = (const float*)d_in[1];
    float* out = (float*)d_out;

    dim3 grid(NCHUNK + 1, B_IMGS);
    box_abs_kernel<<<grid, THREADS>>>(x, y, out);
}